// round 6
// baseline (speedup 1.0000x reference)
#include <cuda_runtime.h>
#include <cstdint>

// ---------------- problem constants ----------------
static constexpr int MDIM = 4096;   // batch
static constexpr int NDIM = 4096;   // out features
static constexpr int KDIM = 4096;   // in features

static constexpr int BM = 128;
static constexpr int BN = 256;
static constexpr int BK = 32;
static constexpr int STAGES  = 4;
static constexpr int THREADS = 512;          // 16 warps: 4 (m) x 4 (n)
static constexpr int KITERS  = KDIM / BK;    // 128

static constexpr uint32_t ASTAGE = BM * BK * 4;            // 16 KB
static constexpr uint32_t BSTAGE = BN * BK * 4;            // 32 KB
static constexpr uint32_t SLOT   = ASTAGE + BSTAGE;        // 48 KB
static constexpr uint32_t SMEM_TOTAL = STAGES * SLOT;      // 192 KB

// ---------------- scratch (device globals: allocations are banned) ----------------
__device__ __align__(1024) float g_wm[(size_t)NDIM * KDIM];  // tf32-rounded masked weight
__device__ __align__(1024) float g_xr[(size_t)MDIM * KDIM];  // tf32-rounded x

// ---------------- sm_80-safe PTX helpers ----------------
__device__ __forceinline__ uint32_t smem_u32(const void* p) {
    uint32_t a;
    asm("{ .reg .u64 t; cvta.to.shared.u64 t, %1; cvt.u32.u64 %0, t; }" : "=r"(a) : "l"(p));
    return a;
}
__device__ __forceinline__ void cp_async16(uint32_t dst, const void* src) {
    asm volatile("cp.async.cg.shared.global [%0], [%1], 16;" :: "r"(dst), "l"(src) : "memory");
}
__device__ __forceinline__ void cp_commit() {
    asm volatile("cp.async.commit_group;" ::: "memory");
}
template <int N>
__device__ __forceinline__ void cp_wait() {
    asm volatile("cp.async.wait_group %0;" :: "n"(N) : "memory");
}
__device__ __forceinline__ void ldsm_x4(uint32_t* r, uint32_t addr) {
    asm volatile("ldmatrix.sync.aligned.m8n8.x4.shared.b16 {%0,%1,%2,%3}, [%4];"
                 : "=r"(r[0]), "=r"(r[1]), "=r"(r[2]), "=r"(r[3]) : "r"(addr));
}
__device__ __forceinline__ void mma_tf32(float* c, const uint32_t* a, const uint32_t* b) {
    asm volatile(
        "mma.sync.aligned.m16n8k8.row.col.f32.tf32.tf32.f32 "
        "{%0,%1,%2,%3}, {%4,%5,%6,%7}, {%8,%9}, {%0,%1,%2,%3};"
        : "+f"(c[0]), "+f"(c[1]), "+f"(c[2]), "+f"(c[3])
        : "r"(a[0]), "r"(a[1]), "r"(a[2]), "r"(a[3]), "r"(b[0]), "r"(b[1]));
}
__device__ __forceinline__ float tf32_rna(float f) {
    uint32_t o, i = __float_as_uint(f);
    asm("cvt.rna.tf32.f32 %0, %1;" : "=r"(o) : "r"(i));
    return __uint_as_float(o);
}

// ---------------- prep: masked weight + tf32 RNA rounding of both operands ----------------
__global__ void prep_kernel(const float4* __restrict__ w, const float4* __restrict__ msk,
                            const float4* __restrict__ x, float4* __restrict__ wm,
                            float4* __restrict__ xr, int n4) {
    int stride = gridDim.x * blockDim.x;
    for (int i = blockIdx.x * blockDim.x + threadIdx.x; i < n4; i += stride) {
        float4 a = w[i], b = msk[i];
        float4 o;
        o.x = tf32_rna(a.x * b.x); o.y = tf32_rna(a.y * b.y);
        o.z = tf32_rna(a.z * b.z); o.w = tf32_rna(a.w * b.w);
        wm[i] = o;
        float4 c = x[i];
        float4 p;
        p.x = tf32_rna(c.x); p.y = tf32_rna(c.y);
        p.z = tf32_rna(c.z); p.w = tf32_rna(c.w);
        xr[i] = p;
    }
}

// ---------------- TF32 mma.sync GEMM: y = X * Wm^T + bias ----------------
// Both operands K-contiguous (row-major [rows][K]) -> symmetric cp.async tiles.
// SMEM rows are 32 floats (128B) with 16B-chunk XOR swizzle: chunk' = chunk ^ (row & 7).
__global__ void __launch_bounds__(THREADS, 1)
gemm_kernel(const float* __restrict__ A,   // g_xr  [M][K]
            const float* __restrict__ B,   // g_wm  [N][K]
            const float* __restrict__ bias,
            float* __restrict__ out) {
    extern __shared__ char smem[];
    const uint32_t sbase = smem_u32(smem);
    const int tid  = threadIdx.x;
    const int lane = tid & 31;
    const int wid  = tid >> 5;
    const int wm   = wid & 3;   // warp m position (x32)
    const int wn   = wid >> 2;  // warp n position (x64)

    const int m0 = blockIdx.x * BM;
    const int n0 = blockIdx.y * BN;
    const float* gA = A + (size_t)m0 * KDIM;
    const float* gB = B + (size_t)n0 * KDIM;

    // -------- stage loader: 6 x 16B cp.async per thread --------
    auto load_stage = [&](int kt, int slot) {
        const uint32_t sA = sbase + slot * SLOT;
        const uint32_t sB = sA + ASTAGE;
        const int kof = kt * BK;
        #pragma unroll
        for (int i = 0; i < 2; i++) {                 // A: 1024 chunks
            int id = tid + THREADS * i;
            int r = id >> 3, c = id & 7;
            cp_async16(sA + r * 128 + ((c ^ (r & 7)) << 4),
                       gA + (size_t)r * KDIM + kof + c * 4);
        }
        #pragma unroll
        for (int i = 0; i < 4; i++) {                 // B: 2048 chunks
            int id = tid + THREADS * i;
            int r = id >> 3, c = id & 7;
            cp_async16(sB + r * 128 + ((c ^ (r & 7)) << 4),
                       gB + (size_t)r * KDIM + kof + c * 4);
        }
    };

    // -------- prologue: stages 0..STAGES-2 --------
    #pragma unroll
    for (int st = 0; st < STAGES - 1; st++) {
        load_stage(st, st);
        cp_commit();
    }

    float acc[2][8][4];
    #pragma unroll
    for (int mt = 0; mt < 2; mt++)
        #pragma unroll
        for (int nt = 0; nt < 8; nt++)
            #pragma unroll
            for (int i = 0; i < 4; i++) acc[mt][nt][i] = 0.0f;

    // -------- main K loop --------
    for (int kt = 0; kt < KITERS; kt++) {
        const int slot = kt & (STAGES - 1);
        cp_wait<STAGES - 2>();
        __syncthreads();

        const int nk = kt + STAGES - 1;
        if (nk < KITERS) load_stage(nk, nk & (STAGES - 1));
        cp_commit();  // always commit (possibly empty) to keep group accounting uniform

        const uint32_t sA = sbase + slot * SLOT;
        const uint32_t sB = sA + ASTAGE;

        #pragma unroll
        for (int s = 0; s < BK / 8; s++) {            // 4 k8 steps
            uint32_t af[2][4], bf[8][2];
            #pragma unroll
            for (int mt = 0; mt < 2; mt++) {
                // x4 mats: [m0-7,k0-3][m8-15,k0-3][m0-7,k4-7][m8-15,k4-7]
                int r = wm * 32 + mt * 16 + (lane & 15);
                int c = 2 * s + (lane >> 4);
                ldsm_x4(af[mt], sA + r * 128 + ((c ^ (r & 7)) << 4));
            }
            #pragma unroll
            for (int p = 0; p < 4; p++) {
                // x4 mats: [n0-7,k0-3][n0-7,k4-7][n8-15,k0-3][n8-15,k4-7]
                int r = wn * 64 + p * 16 + (lane & 7) + ((lane >> 4) << 3);
                int c = 2 * s + ((lane >> 3) & 1);
                uint32_t t[4];
                ldsm_x4(t, sB + r * 128 + ((c ^ (r & 7)) << 4));
                bf[2 * p][0] = t[0]; bf[2 * p][1] = t[1];
                bf[2 * p + 1][0] = t[2]; bf[2 * p + 1][1] = t[3];
            }
            #pragma unroll
            for (int mt = 0; mt < 2; mt++)
                #pragma unroll
                for (int nt = 0; nt < 8; nt++)
                    mma_tf32(acc[mt][nt], af[mt], bf[nt]);
        }
    }
    cp_wait<0>();  // drain tail groups before exit

    // -------- epilogue: bias add + float2 stores --------
    const int r  = lane >> 2;
    const int c2 = (lane & 3) * 2;
    const float* bp = bias + n0 + wn * 64;
    float* op = out + (size_t)(m0 + wm * 32) * NDIM + n0 + wn * 64;

    #pragma unroll
    for (int mt = 0; mt < 2; mt++) {
        #pragma unroll
        for (int nt = 0; nt < 8; nt++) {
            int n = nt * 8 + c2;
            float b0 = __ldg(bp + n), b1 = __ldg(bp + n + 1);
            float2 v0 = {acc[mt][nt][0] + b0, acc[mt][nt][1] + b1};
            float2 v1 = {acc[mt][nt][2] + b0, acc[mt][nt][3] + b1};
            *reinterpret_cast<float2*>(op + (size_t)(mt * 16 + r) * NDIM + n) = v0;
            *reinterpret_cast<float2*>(op + (size_t)(mt * 16 + r + 8) * NDIM + n) = v1;
        }
    }
}

// ---------------- host ----------------
extern "C" void kernel_launch(void* const* d_in, const int* in_sizes, int n_in,
                              void* d_out, int out_size) {
    const float* x    = (const float*)d_in[0];
    const float* w    = (const float*)d_in[1];
    const float* bias = (const float*)d_in[2];
    const float* msk  = (const float*)d_in[3];
    float* out = (float*)d_out;

    void* wm_ptr = nullptr;
    void* xr_ptr = nullptr;
    cudaGetSymbolAddress(&wm_ptr, g_wm);
    cudaGetSymbolAddress(&xr_ptr, g_xr);

    // prep: W*M with tf32 RNA rounding, x with tf32 RNA rounding
    int n4 = (KDIM * NDIM) / 4;
    prep_kernel<<<4096, 256>>>((const float4*)w, (const float4*)msk, (const float4*)x,
                               (float4*)wm_ptr, (float4*)xr_ptr, n4);

    cudaFuncSetAttribute(gemm_kernel, cudaFuncAttributeMaxDynamicSharedMemorySize,
                         (int)SMEM_TOTAL);

    // m fastest in blockIdx.x: one wave (~148 CTAs) covers all 32 m-tiles x ~4.6 n-tiles,
    // keeping the full 64MB A matrix L2-resident across the kernel.
    dim3 grid(MDIM / BM, NDIM / BN, 1);  // (32, 16)
    gemm_kernel<<<grid, THREADS, SMEM_TOTAL>>>((const float*)xr_ptr, (const float*)wm_ptr,
                                               bias, out);
}

// round 7
// speedup vs baseline: 1.1544x; 1.1544x over previous
#include <cuda_runtime.h>
#include <cstdint>

// ---------------- problem constants ----------------
static constexpr int MDIM = 4096;   // batch
static constexpr int NDIM = 4096;   // out features
static constexpr int KDIM = 4096;   // in features

static constexpr int BM = 128;
static constexpr int BN = 128;
static constexpr int BK = 32;
static constexpr int STAGES  = 3;
static constexpr int THREADS = 256;          // 8 warps: 4 (m) x 2 (n), warp tile 32x64
static constexpr int KITERS  = KDIM / BK;    // 128

static constexpr uint32_t ASTAGE = BM * BK * 4;            // 16 KB
static constexpr uint32_t BSTAGE = BN * BK * 4;            // 16 KB
static constexpr uint32_t SLOT   = ASTAGE + BSTAGE;        // 32 KB
static constexpr uint32_t SMEM_TOTAL = STAGES * SLOT;      // 96 KB -> 2 CTAs/SM

// ---------------- scratch (device globals: allocations are banned) ----------------
__device__ __align__(1024) float g_wm[(size_t)NDIM * KDIM];  // tf32-rounded masked weight
__device__ __align__(1024) float g_xr[(size_t)MDIM * KDIM];  // tf32-rounded x

// ---------------- sm_80-safe PTX helpers ----------------
__device__ __forceinline__ uint32_t smem_u32(const void* p) {
    uint32_t a;
    asm("{ .reg .u64 t; cvta.to.shared.u64 t, %1; cvt.u32.u64 %0, t; }" : "=r"(a) : "l"(p));
    return a;
}
__device__ __forceinline__ void cp_async16(uint32_t dst, const void* src) {
    asm volatile("cp.async.cg.shared.global [%0], [%1], 16;" :: "r"(dst), "l"(src) : "memory");
}
__device__ __forceinline__ void cp_commit() {
    asm volatile("cp.async.commit_group;" ::: "memory");
}
template <int N>
__device__ __forceinline__ void cp_wait() {
    asm volatile("cp.async.wait_group %0;" :: "n"(N) : "memory");
}
__device__ __forceinline__ void ldsm_x4(uint32_t* r, uint32_t addr) {
    asm volatile("ldmatrix.sync.aligned.m8n8.x4.shared.b16 {%0,%1,%2,%3}, [%4];"
                 : "=r"(r[0]), "=r"(r[1]), "=r"(r[2]), "=r"(r[3]) : "r"(addr));
}
__device__ __forceinline__ void mma_tf32(float* c, const uint32_t* a, const uint32_t* b) {
    asm volatile(
        "mma.sync.aligned.m16n8k8.row.col.f32.tf32.tf32.f32 "
        "{%0,%1,%2,%3}, {%4,%5,%6,%7}, {%8,%9}, {%0,%1,%2,%3};"
        : "+f"(c[0]), "+f"(c[1]), "+f"(c[2]), "+f"(c[3])
        : "r"(a[0]), "r"(a[1]), "r"(a[2]), "r"(a[3]), "r"(b[0]), "r"(b[1]));
}
__device__ __forceinline__ float tf32_rna(float f) {
    uint32_t o, i = __float_as_uint(f);
    asm("cvt.rna.tf32.f32 %0, %1;" : "=r"(o) : "r"(i));
    return __uint_as_float(o);
}

// ---------------- prep: masked weight + tf32 RNA rounding of both operands ----------------
__global__ void prep_kernel(const float4* __restrict__ w, const float4* __restrict__ msk,
                            const float4* __restrict__ x, float4* __restrict__ wm,
                            float4* __restrict__ xr, int n4) {
    int stride = gridDim.x * blockDim.x;
    for (int i = blockIdx.x * blockDim.x + threadIdx.x; i < n4; i += stride) {
        float4 a = w[i], b = msk[i];
        float4 o;
        o.x = tf32_rna(a.x * b.x); o.y = tf32_rna(a.y * b.y);
        o.z = tf32_rna(a.z * b.z); o.w = tf32_rna(a.w * b.w);
        wm[i] = o;
        float4 c = x[i];
        float4 p;
        p.x = tf32_rna(c.x); p.y = tf32_rna(c.y);
        p.z = tf32_rna(c.z); p.w = tf32_rna(c.w);
        xr[i] = p;
    }
}

// ---------------- TF32 mma.sync GEMM: y = X * Wm^T + bias ----------------
// Both operands K-contiguous (row-major [rows][K]) -> symmetric cp.async tiles.
// SMEM rows are 32 floats (128B) with 16B-chunk XOR swizzle: chunk' = chunk ^ (row & 7).
// 2 CTAs/SM (96KB smem, <=128 regs): cross-CTA overlap hides barriers + LDSM latency.
__global__ void __launch_bounds__(THREADS, 2)
gemm_kernel(const float* __restrict__ A,   // g_xr  [M][K]
            const float* __restrict__ B,   // g_wm  [N][K]
            const float* __restrict__ bias,
            float* __restrict__ out) {
    extern __shared__ char smem[];
    const uint32_t sbase = smem_u32(smem);
    const int tid  = threadIdx.x;
    const int lane = tid & 31;
    const int wid  = tid >> 5;
    const int wm   = wid & 3;   // warp m position (x32): 4
    const int wn   = wid >> 2;  // warp n position (x64): 2

    const int m0 = blockIdx.x * BM;
    const int n0 = blockIdx.y * BN;
    const float* gA = A + (size_t)m0 * KDIM;
    const float* gB = B + (size_t)n0 * KDIM;

    // -------- stage loader: 8 x 16B cp.async per thread --------
    auto load_stage = [&](int kt, int slot) {
        const uint32_t sA = sbase + slot * SLOT;
        const uint32_t sB = sA + ASTAGE;
        const int kof = kt * BK;
        #pragma unroll
        for (int i = 0; i < 4; i++) {                 // A: 1024 chunks
            int id = tid + THREADS * i;
            int r = id >> 3, c = id & 7;
            cp_async16(sA + r * 128 + ((c ^ (r & 7)) << 4),
                       gA + (size_t)r * KDIM + kof + c * 4);
        }
        #pragma unroll
        for (int i = 0; i < 4; i++) {                 // B: 1024 chunks
            int id = tid + THREADS * i;
            int r = id >> 3, c = id & 7;
            cp_async16(sB + r * 128 + ((c ^ (r & 7)) << 4),
                       gB + (size_t)r * KDIM + kof + c * 4);
        }
    };

    // -------- prologue: stages 0..STAGES-2 --------
    #pragma unroll
    for (int st = 0; st < STAGES - 1; st++) {
        load_stage(st, st);
        cp_commit();
    }

    float acc[2][8][4];
    #pragma unroll
    for (int mt = 0; mt < 2; mt++)
        #pragma unroll
        for (int nt = 0; nt < 8; nt++)
            #pragma unroll
            for (int i = 0; i < 4; i++) acc[mt][nt][i] = 0.0f;

    // -------- main K loop --------
    int slot = 0;
    for (int kt = 0; kt < KITERS; kt++) {
        cp_wait<STAGES - 2>();
        __syncthreads();

        const int nk = kt + STAGES - 1;
        int nslot = slot + 1; if (nslot == STAGES) nslot = 0;
        if (nk < KITERS) {
            int ls = nk % STAGES;
            load_stage(nk, ls);
        }
        cp_commit();  // always commit (possibly empty) to keep group accounting uniform

        const uint32_t sA = sbase + slot * SLOT;
        const uint32_t sB = sA + ASTAGE;

        #pragma unroll
        for (int s = 0; s < BK / 8; s++) {            // 4 k8 steps
            uint32_t af[2][4], bf[8][2];
            #pragma unroll
            for (int mt = 0; mt < 2; mt++) {
                // x4 mats: [m0-7,k0-3][m8-15,k0-3][m0-7,k4-7][m8-15,k4-7]
                int r = wm * 32 + mt * 16 + (lane & 15);
                int c = 2 * s + (lane >> 4);
                ldsm_x4(af[mt], sA + r * 128 + ((c ^ (r & 7)) << 4));
            }
            #pragma unroll
            for (int p = 0; p < 4; p++) {
                // x4 mats: [n0-7,k0-3][n0-7,k4-7][n8-15,k0-3][n8-15,k4-7]
                int r = wn * 64 + p * 16 + (lane & 7) + ((lane >> 4) << 3);
                int c = 2 * s + ((lane >> 3) & 1);
                uint32_t t[4];
                ldsm_x4(t, sB + r * 128 + ((c ^ (r & 7)) << 4));
                bf[2 * p][0] = t[0]; bf[2 * p][1] = t[1];
                bf[2 * p + 1][0] = t[2]; bf[2 * p + 1][1] = t[3];
            }
            #pragma unroll
            for (int mt = 0; mt < 2; mt++)
                #pragma unroll
                for (int nt = 0; nt < 8; nt++)
                    mma_tf32(acc[mt][nt], af[mt], bf[nt]);
        }
        slot = nslot;
    }
    cp_wait<0>();  // drain tail groups before exit

    // -------- epilogue: bias add + float2 stores --------
    const int r  = lane >> 2;
    const int c2 = (lane & 3) * 2;
    const float* bp = bias + n0 + wn * 64;
    float* op = out + (size_t)(m0 + wm * 32) * NDIM + n0 + wn * 64;

    #pragma unroll
    for (int mt = 0; mt < 2; mt++) {
        #pragma unroll
        for (int nt = 0; nt < 8; nt++) {
            int n = nt * 8 + c2;
            float b0 = __ldg(bp + n), b1 = __ldg(bp + n + 1);
            float2 v0 = {acc[mt][nt][0] + b0, acc[mt][nt][1] + b1};
            float2 v1 = {acc[mt][nt][2] + b0, acc[mt][nt][3] + b1};
            *reinterpret_cast<float2*>(op + (size_t)(mt * 16 + r) * NDIM + n) = v0;
            *reinterpret_cast<float2*>(op + (size_t)(mt * 16 + r + 8) * NDIM + n) = v1;
        }
    }
}

// ---------------- host ----------------
extern "C" void kernel_launch(void* const* d_in, const int* in_sizes, int n_in,
                              void* d_out, int out_size) {
    const float* x    = (const float*)d_in[0];
    const float* w    = (const float*)d_in[1];
    const float* bias = (const float*)d_in[2];
    const float* msk  = (const float*)d_in[3];
    float* out = (float*)d_out;

    void* wm_ptr = nullptr;
    void* xr_ptr = nullptr;
    cudaGetSymbolAddress(&wm_ptr, g_wm);
    cudaGetSymbolAddress(&xr_ptr, g_xr);

    // prep: W*M with tf32 RNA rounding, x with tf32 RNA rounding
    int n4 = (KDIM * NDIM) / 4;
    prep_kernel<<<4096, 256>>>((const float4*)w, (const float4*)msk, (const float4*)x,
                               (float4*)wm_ptr, (float4*)xr_ptr, n4);

    cudaFuncSetAttribute(gemm_kernel, cudaFuncAttributeMaxDynamicSharedMemorySize,
                         (int)SMEM_TOTAL);

    // m fastest in blockIdx.x: each ~296-CTA wave covers all 32 m-tiles for ~9 n-tiles,
    // keeping the 64MB A matrix L2-resident across the kernel (L2 was at 10.9%).
    dim3 grid(MDIM / BM, NDIM / BN, 1);  // (32, 32)
    gemm_kernel<<<grid, THREADS, SMEM_TOTAL>>>((const float*)xr_ptr, (const float*)wm_ptr,
                                               bias, out);
}